// round 14
// baseline (speedup 1.0000x reference)
#include <cuda_runtime.h>
#include <cstdint>

typedef unsigned long long ull;

// ---------------- problem constants ----------------
#define T_STEPS 2048
#define BATCH   64
#define FEAT    13
#define HID     300
#define OUT_MAIN (BATCH*T_STEPS*FEAT)
#define OUT_EMB_OFF OUT_MAIN

// ---------------- encoder config ----------------
#define CLUSTER 8
#define NGROUP  2
#define NBG     2               // batch per group
#define NB      (NGROUP*NBG)    // 4 per cluster
#define TENC    576             // 480 gemm + 96 gate/publish
#define NGEMM   480
#define HC      38              // hidden units per CTA chunk
#define ROWP    40              // padded rows per gate
#define R3      120
#define KSPLIT  8
#define KSEG2   19              // k-pairs per split (38 floats)
#define RG      60
#define CHUNKF  (NBG*HC)        // 76 floats per CTA per group per step
#define CHUNKB  (CHUNKF*4)      // 304 B

#define BAR_PART_A 1
#define BAR_PART_B 2
#define BAR_GATES  3

__device__ float g_hlast[BATCH*HID];
__device__ float g_emb[BATCH*HID];

// ---------------- helpers ----------------
__device__ __forceinline__ float sig_f(float x) {
    return __fdividef(1.f, 1.f + __expf(-x));
}
__device__ __forceinline__ float tanh_f(float x) {
    return 1.f - __fdividef(2.f, __expf(2.f * x) + 1.f);
}
__device__ __forceinline__ unsigned smem_u32(const void* p) {
    unsigned a;
    asm("{ .reg .u64 t; cvta.to.shared.u64 t, %1; cvt.u32.u64 %0, t; }"
        : "=r"(a) : "l"(p));
    return a;
}
__device__ __forceinline__ void cluster_sync_() {
    asm volatile("barrier.cluster.arrive.aligned;" ::: "memory");
    asm volatile("barrier.cluster.wait.aligned;" ::: "memory");
}
__device__ __forceinline__ ull pk2(float lo, float hi) {
    ull r;
    asm("mov.b64 %0, {%1, %2};" : "=l"(r) : "f"(lo), "f"(hi));
    return r;
}
__device__ __forceinline__ void fma2(ull& d, ull a, ull b) {
    asm("fma.rn.f32x2 %0, %1, %2, %0;" : "+l"(d) : "l"(a), "l"(b));
}
__device__ __forceinline__ float upks(ull v) {
    float lo, hi;
    asm("mov.b64 {%0, %1}, %2;" : "=f"(lo), "=f"(hi) : "l"(v));
    return lo + hi;
}
__device__ __forceinline__ unsigned mapa_(unsigned a, int rank) {
    unsigned r;
    asm("mapa.shared::cluster.u32 %0, %1, %2;" : "=r"(r) : "r"(a), "r"(rank));
    return r;
}
__device__ __forceinline__ void mbar_init(unsigned a, unsigned cnt) {
    asm volatile("mbarrier.init.shared.b64 [%0], %1;" :: "r"(a), "r"(cnt) : "memory");
}
// acquire at CLUSTER scope: orders subsequent reads of remotely-written SMEM
__device__ __forceinline__ void mbar_wait_cl(unsigned a, unsigned par) {
    unsigned done;
    asm volatile(
        "{\n\t.reg .pred p;\n\t"
        "mbarrier.try_wait.parity.acquire.cluster.shared::cta.b64 p, [%1], %2;\n\t"
        "selp.b32 %0, 1, 0, p;\n\t}"
        : "=r"(done) : "r"(a), "r"(par) : "memory");
    if (!done) {
        asm volatile(
            "{\n\t.reg .pred P1;\n"
            "WAIT_%=:\n\t"
            "mbarrier.try_wait.parity.acquire.cluster.shared::cta.b64 P1, [%0], %1, 0x989680;\n\t"
            "@P1 bra DONE_%=;\n\t"
            "bra WAIT_%=;\n"
            "DONE_%=:\n\t}"
            :: "r"(a), "r"(par) : "memory");
    }
}
// remote arrive with release.cluster (orders THIS thread's prior remote stores)
__device__ __forceinline__ void mbar_arrive_remote(unsigned local_addr, int rank) {
    unsigned ra = mapa_(local_addr, rank);
    asm volatile("mbarrier.arrive.release.cluster.shared::cluster.b64 _, [%0];"
                 :: "r"(ra) : "memory");
}
__device__ __forceinline__ void st_remote_u64(unsigned raddr, ull v) {
    asm volatile("st.shared::cluster.b64 [%0], %1;" :: "r"(raddr), "l"(v) : "memory");
}
__device__ __forceinline__ void bar_arrive(int id, int cnt) {
    asm volatile("bar.arrive %0, %1;" :: "r"(id), "r"(cnt) : "memory");
}
__device__ __forceinline__ void bar_sync(int id, int cnt) {
    asm volatile("bar.sync %0, %1;" :: "r"(id), "r"(cnt) : "memory");
}

// ======================================================================
// Encoder: R9 two-group pipeline; publish = SIMT scalar DSMEM copy.
// 8 publisher lanes (one warp) each copy the 304B chunk to one dest CTA
// with 38x b64 remote stores (lockstep, broadcast reads), then ONE
// release-arrive each. Count-8 dest barriers; acquire.cluster waits.
// No TMA, no proxy fences, no engine serialization.
// ======================================================================
__global__ void __launch_bounds__(TENC, 1) __cluster_dims__(CLUSTER, 1, 1)
enc_kernel(const float* __restrict__ x,
           const float* __restrict__ Wih,
           const float* __restrict__ Whh,
           const float* __restrict__ bih,
           const float* __restrict__ bhh)
{
    __shared__ __align__(16) float  hbuf[NGROUP][2][CLUSTER][NBG][HC]; // 9728 B
    __shared__ __align__(16) float2 part[NGROUP][2][NBG][KSPLIT][RG];  // 30720 B
    __shared__ __align__(16) float  xst[NGROUP][2][NBG][14];           // 896 B
    __shared__ ull mbars[NGROUP][2];

    const int tid = threadIdx.x;
    unsigned rank;
    asm("mov.u32 %0, %%cluster_ctarank;" : "=r"(rank));
    const int bg = (blockIdx.x / CLUSTER) * NB;

    // ---- zero buffers ----
    {
        float* hf = (float*)hbuf;
        for (int i = tid; i < NGROUP * 2 * CLUSTER * NBG * HC; i += TENC) hf[i] = 0.f;
        float* xf = (float*)xst;
        for (int i = tid; i < NGROUP * 2 * NBG * 14; i += TENC) xf[i] = 0.f;
    }
    // prime x(0)
    if (tid < NGROUP * NBG * FEAT) {
        int g = tid / (NBG * FEAT), r = tid % (NBG * FEAT);
        int b = r / FEAT, f = r % FEAT;
        xst[g][0][b][f] = x[((long)(bg + g * NBG + b) * T_STEPS) * FEAT + f];
    }

    const unsigned barb  = smem_u32(&mbars[0][0]);
    const unsigned hbase = smem_u32(hbuf);
    if (tid == 0) {
#pragma unroll
        for (int i = 0; i < 4; i++) mbar_init(barb + i * 8u, CLUSTER);
    }
    __syncthreads();

    if (tid < NGEMM) {
        // =================== GEMM role ===================
        const int ks = tid / RG;
        const int rg = tid % RG;
        const int row0 = rg * 2;
        ull w0[KSEG2], w1[KSEG2];
        {
            int ga = row0 / ROWP, ia = row0 % ROWP, ua = (int)rank * HC + ia;
            bool oka = (ia < HC) && (ua < HID);
            int gb2 = (row0 + 1) / ROWP, ib = (row0 + 1) % ROWP, ub = (int)rank * HC + ib;
            bool okb = (ib < HC) && (ub < HID);
#pragma unroll
            for (int kp = 0; kp < KSEG2; kp++) {
                int k0 = ks * HC + 2 * kp, k1 = k0 + 1;
                float a0 = (oka && k0 < HID) ? Whh[(ga * HID + ua) * HID + k0] : 0.f;
                float b0 = (oka && k1 < HID) ? Whh[(ga * HID + ua) * HID + k1] : 0.f;
                float a1 = (okb && k0 < HID) ? Whh[(gb2 * HID + ub) * HID + k0] : 0.f;
                float b1 = (okb && k1 < HID) ? Whh[(gb2 * HID + ub) * HID + k1] : 0.f;
                w0[kp] = pk2(a0, b0);
                w1[kp] = pk2(a1, b1);
            }
        }
        __syncthreads();
        cluster_sync_();

        for (int t = 0; t < T_STEPS; t++) {
            const int p = t & 1;
#pragma unroll
            for (int g = 0; g < NGROUP; g++) {
                if (t) {
                    const unsigned bw = barb + (unsigned)(g * 2 + ((t - 1) & 1)) * 8u;
                    mbar_wait_cl(bw, (unsigned)(((t - 1) >> 1) & 1));
                }
                // GEMM over buf p: h chunks are rank-major, k = ks*38 + j
                const ull* hp = (const ull*)&hbuf[g][p][ks][0][0];
                ull a00 = 0, a01 = 0, a10 = 0, a11 = 0;
#pragma unroll
                for (int kp = 0; kp < KSEG2; kp++) {
                    ull h0 = hp[kp];
                    ull h1 = hp[kp + KSEG2];
                    fma2(a00, w0[kp], h0); fma2(a01, w1[kp], h0);
                    fma2(a10, w0[kp], h1); fma2(a11, w1[kp], h1);
                }
                part[g][p][0][ks][rg] = make_float2(upks(a00), upks(a01));
                part[g][p][1][ks][rg] = make_float2(upks(a10), upks(a11));
                bar_arrive(g == 0 ? BAR_PART_A : BAR_PART_B, TENC);
            }
        }
    } else {
        // =================== gate + publish role (96 threads) ===================
        const int gt = tid - NGEMM;
        const int gb2 = gt / HC;          // 0/1 within group
        const int gi_ = gt % HC;
        const int u_g = (int)rank * HC + gi_;
        const bool active = (gt < NBG * HC) && (u_g < HID);

        ull wihr[3][7];
        float brz0 = 0.f, brz1 = 0.f, bin_ = 0.f, bhn_ = 0.f;
        float h_keep[NGROUP] = {0.f, 0.f};
        if (active) {
#pragma unroll
            for (int g = 0; g < 3; g++)
#pragma unroll
                for (int fp = 0; fp < 7; fp++) {
                    float a = Wih[(g * HID + u_g) * FEAT + 2 * fp];
                    float b = (2 * fp + 1 < FEAT) ? Wih[(g * HID + u_g) * FEAT + 2 * fp + 1] : 0.f;
                    wihr[g][fp] = pk2(a, b);
                }
            brz0 = bih[u_g]           + bhh[u_g];
            brz1 = bih[HID + u_g]     + bhh[HID + u_g];
            bin_ = bih[2 * HID + u_g];
            bhn_ = bhh[2 * HID + u_g];
        }
        __syncthreads();
        cluster_sync_();

        for (int t = 0; t < T_STEPS; t++) {
            const int p = t & 1;
            const int buf = p ^ 1;
#pragma unroll
            for (int g = 0; g < NGROUP; g++) {
                bar_sync(g == 0 ? BAR_PART_A : BAR_PART_B, TENC);

                // x prefetch for t+1 (this group's 2 batches)
                if (gt < NBG * FEAT && t + 1 < T_STEPS) {
                    int b = gt / FEAT, f = gt % FEAT;
                    xst[g][buf][b][f] =
                        __ldg(&x[((long)(bg + g * NBG + b) * T_STEPS + t + 1) * FEAT + f]);
                }

                if (active) {
                    const float* pf = (const float*)&part[g][p][gb2][0][0];
                    float s0 = 0.f, s1 = 0.f, s2 = 0.f;
#pragma unroll
                    for (int q = 0; q < KSPLIT; q++) {
                        const int base = q * R3;
                        s0 += pf[base + gi_];
                        s1 += pf[base + ROWP + gi_];
                        s2 += pf[base + 2 * ROWP + gi_];
                    }
                    ull d0 = 0, d1 = 0, d2 = 0;
                    const ull* xq = (const ull*)&xst[g][p][gb2][0];
#pragma unroll
                    for (int fp = 0; fp < 7; fp++) {
                        ull xv = xq[fp];
                        fma2(d0, wihr[0][fp], xv);
                        fma2(d1, wihr[1][fp], xv);
                        fma2(d2, wihr[2][fp], xv);
                    }
                    const float r = sig_f(upks(d0) + s0 + brz0);
                    const float z = sig_f(upks(d1) + s1 + brz1);
                    const float n = tanh_f(upks(d2) + bin_ + r * (s2 + bhn_));
                    const float hn = (1.f - z) * n + z * h_keep[g];
                    h_keep[g] = hn;
                    hbuf[g][buf][rank][gb2][gi_] = hn;   // local chunk write
                }
                bar_sync(BAR_GATES, TENC - NGEMM);   // drains STS: chunk visible

                // ---- publish: lanes 0..7 copy the chunk to dest gt (lockstep) ----
                if (t + 1 < T_STEPS && gt < CLUSTER) {
                    const unsigned off =
                        (unsigned)(((g * 2 + buf) * CLUSTER + (int)rank) * CHUNKB);
                    const ull* sp = (const ull*)((const float*)hbuf
                        + ((g * 2 + buf) * CLUSTER + (int)rank) * CHUNKF);
                    const unsigned dstb = mapa_(hbase + off, gt);
#pragma unroll
                    for (int j = 0; j < CHUNKF / 2; j++)
                        st_remote_u64(dstb + (unsigned)j * 8u, sp[j]);
                    // release orders this thread's stores before its arrive
                    mbar_arrive_remote(barb + (unsigned)(g * 2 + (t & 1)) * 8u, gt);
                }
            }
        }

        if (active) {
#pragma unroll
            for (int g = 0; g < NGROUP; g++)
                g_hlast[(bg + g * NBG + gb2) * HID + u_g] = h_keep[g];
        }
    }

    // no CTA may exit while sibling remote stores into it may be in flight
    cluster_sync_();
}

// ======================================================================
// fc + relu
// ======================================================================
__global__ void __launch_bounds__(128) fc_kernel(
    const float* __restrict__ fcW, const float* __restrict__ fcb,
    float* __restrict__ dout, int write_emb)
{
    __shared__ float hs[HID];
    const int b = blockIdx.x;
    const int tid = threadIdx.x;
    for (int k = tid; k < HID; k += 128) hs[k] = g_hlast[b * HID + k];
    __syncthreads();
    for (int j = tid; j < HID; j += 128) {
        float a = fcb[j];
        const float* w = fcW + j * HID;
#pragma unroll 4
        for (int k = 0; k < HID; k++) a = fmaf(w[k], hs[k], a);
        a = fmaxf(a, 0.f);
        g_emb[b * HID + j] = a;
        if (write_emb) dout[OUT_EMB_OFF + b * HID + j] = a;
    }
}

// ======================================================================
// Decoder: one warp per batch element, h broadcast via shfl.
// ======================================================================
__global__ void __launch_bounds__(32) dec_kernel(
    const float* __restrict__ dWih, const float* __restrict__ dWhh,
    const float* __restrict__ dbih, const float* __restrict__ dbhh,
    float* __restrict__ out)
{
    const int b = blockIdx.x;
    const int lane = threadIdx.x;

    float wr[FEAT], wz[FEAT], wn[FEAT];
    float gr0 = 0.f, gz0 = 0.f, gn0 = 0.f, bhn = 0.f, h = 0.f;

    if (lane < FEAT) {
        gr0 = dbih[lane]            + dbhh[lane];
        gz0 = dbih[FEAT + lane]     + dbhh[FEAT + lane];
        gn0 = dbih[2 * FEAT + lane];
        bhn = dbhh[2 * FEAT + lane];
        const float* e  = g_emb + b * HID;
        const float* w0 = dWih + lane * HID;
        const float* w1 = dWih + (FEAT + lane) * HID;
        const float* w2 = dWih + (2 * FEAT + lane) * HID;
#pragma unroll 4
        for (int k = 0; k < HID; k++) {
            float ev = e[k];
            gr0 = fmaf(w0[k], ev, gr0);
            gz0 = fmaf(w1[k], ev, gz0);
            gn0 = fmaf(w2[k], ev, gn0);
        }
#pragma unroll
        for (int k = 0; k < FEAT; k++) {
            wr[k] = dWhh[lane * FEAT + k];
            wz[k] = dWhh[(FEAT + lane) * FEAT + k];
            wn[k] = dWhh[(2 * FEAT + lane) * FEAT + k];
        }
    }

    float* ob = out + (long)b * T_STEPS * FEAT;
    for (int t = 0; t < T_STEPS; t++) {
        float sr = 0.f, sz = 0.f, sn = 0.f;
#pragma unroll
        for (int k = 0; k < FEAT; k++) {
            float hk = __shfl_sync(0xffffffffu, h, k);
            sr = fmaf(wr[k], hk, sr);
            sz = fmaf(wz[k], hk, sz);
            sn = fmaf(wn[k], hk, sn);
        }
        if (lane < FEAT) {
            float r = sig_f(gr0 + sr);
            float z = sig_f(gz0 + sz);
            float n = tanh_f(gn0 + r * (sn + bhn));
            h = (1.f - z) * n + z * h;
            ob[t * FEAT + lane] = h;
        }
    }
}

// ======================================================================
// launch
// ======================================================================
extern "C" void kernel_launch(void* const* d_in, const int* in_sizes, int n_in,
                              void* d_out, int out_size)
{
    const float* x        = (const float*)d_in[0];
    const float* enc_Wih  = (const float*)d_in[1];
    const float* enc_Whh  = (const float*)d_in[2];
    const float* enc_bih  = (const float*)d_in[3];
    const float* enc_bhh  = (const float*)d_in[4];
    const float* fc_W     = (const float*)d_in[5];
    const float* fc_b     = (const float*)d_in[6];
    const float* dec_Wih  = (const float*)d_in[7];
    const float* dec_Whh  = (const float*)d_in[8];
    const float* dec_bih  = (const float*)d_in[9];
    const float* dec_bhh  = (const float*)d_in[10];
    float* out = (float*)d_out;

    const int write_emb = (out_size >= OUT_MAIN + BATCH * HID) ? 1 : 0;

    enc_kernel<<<(BATCH / NB) * CLUSTER, TENC>>>(
        x, enc_Wih, enc_Whh, enc_bih, enc_bhh);
    fc_kernel<<<BATCH, 128>>>(fc_W, fc_b, out, write_emb);
    dec_kernel<<<BATCH, 32>>>(dec_Wih, dec_Whh, dec_bih, dec_bhh, out);
}

// round 15
// speedup vs baseline: 1.8096x; 1.8096x over previous
#include <cuda_runtime.h>
#include <cstdint>

typedef unsigned long long ull;

// ---------------- problem constants ----------------
#define T_STEPS 2048
#define BATCH   64
#define FEAT    13
#define HID     300
#define OUT_MAIN (BATCH*T_STEPS*FEAT)
#define OUT_EMB_OFF OUT_MAIN

// ---------------- encoder config ----------------
#define CLUSTER 8
#define NGROUP  2
#define NBG     2               // batch per group
#define NB      (NGROUP*NBG)    // 4 per cluster
#define TENC    576             // 480 gemm + 96 gate/publish
#define NGEMM   480
#define HC      38              // hidden units per CTA chunk
#define ROWP    40              // padded rows per gate
#define KSPLIT  8
#define KSEG2   19              // k-pairs per split (38 floats)
#define RG      60
#define CHUNKF  (NBG*HC)        // 76 floats per CTA per group per step
#define CHUNKB  (CHUNKF*4)      // 304 B
#define EXPB    (CLUSTER*CHUNKB) // 2432 B expected per group-step

#define BAR_PART_A 1
#define BAR_PART_B 2
#define BAR_GATES  3

__device__ float g_hlast[BATCH*HID];
__device__ float g_emb[BATCH*HID];

// ---------------- helpers ----------------
__device__ __forceinline__ float sig_f(float x) {
    return __fdividef(1.f, 1.f + __expf(-x));
}
__device__ __forceinline__ float tanh_f(float x) {
    return 1.f - __fdividef(2.f, __expf(2.f * x) + 1.f);
}
__device__ __forceinline__ unsigned smem_u32(const void* p) {
    unsigned a;
    asm("{ .reg .u64 t; cvta.to.shared.u64 t, %1; cvt.u32.u64 %0, t; }"
        : "=r"(a) : "l"(p));
    return a;
}
__device__ __forceinline__ void cluster_sync_() {
    asm volatile("barrier.cluster.arrive.aligned;" ::: "memory");
    asm volatile("barrier.cluster.wait.aligned;" ::: "memory");
}
__device__ __forceinline__ ull pk2(float lo, float hi) {
    ull r;
    asm("mov.b64 %0, {%1, %2};" : "=l"(r) : "f"(lo), "f"(hi));
    return r;
}
__device__ __forceinline__ void fma2(ull& d, ull a, ull b) {
    asm("fma.rn.f32x2 %0, %1, %2, %0;" : "+l"(d) : "l"(a), "l"(b));
}
__device__ __forceinline__ float upks(ull v) {
    float lo, hi;
    asm("mov.b64 {%0, %1}, %2;" : "=f"(lo), "=f"(hi) : "l"(v));
    return lo + hi;
}
__device__ __forceinline__ unsigned mapa_(unsigned a, int rank) {
    unsigned r;
    asm("mapa.shared::cluster.u32 %0, %1, %2;" : "=r"(r) : "r"(a), "r"(rank));
    return r;
}
__device__ __forceinline__ void mbar_init(unsigned a, unsigned cnt) {
    asm volatile("mbarrier.init.shared.b64 [%0], %1;" :: "r"(a), "r"(cnt) : "memory");
}
__device__ __forceinline__ void mbar_expect(unsigned a, unsigned bytes) {
    asm volatile("mbarrier.arrive.expect_tx.shared.b64 _, [%0], %1;"
                 :: "r"(a), "r"(bytes) : "memory");
}
__device__ __forceinline__ void mbar_wait(unsigned a, unsigned par) {
    unsigned done;
    asm volatile(
        "{\n\t.reg .pred p;\n\t"
        "mbarrier.try_wait.parity.acquire.cta.shared::cta.b64 p, [%1], %2;\n\t"
        "selp.b32 %0, 1, 0, p;\n\t}"
        : "=r"(done) : "r"(a), "r"(par) : "memory");
    if (!done) {
        asm volatile(
            "{\n\t.reg .pred P1;\n"
            "WAIT_%=:\n\t"
            "mbarrier.try_wait.parity.acquire.cta.shared::cta.b64 P1, [%0], %1, 0x989680;\n\t"
            "@P1 bra DONE_%=;\n\t"
            "bra WAIT_%=;\n"
            "DONE_%=:\n\t}"
            :: "r"(a), "r"(par) : "memory");
    }
}
__device__ __forceinline__ void bulk_copy_cluster(unsigned dst, unsigned src,
                                                  unsigned bytes, unsigned rbar) {
    asm volatile(
        "cp.async.bulk.shared::cluster.shared::cta.mbarrier::complete_tx::bytes "
        "[%0], [%1], %2, [%3];"
        :: "r"(dst), "r"(src), "r"(bytes), "r"(rbar) : "memory");
}
__device__ __forceinline__ void fence_async_() {
    asm volatile("fence.proxy.async.shared::cta;" ::: "memory");
}
__device__ __forceinline__ void bar_arrive(int id, int cnt) {
    asm volatile("bar.arrive %0, %1;" :: "r"(id), "r"(cnt) : "memory");
}
__device__ __forceinline__ void bar_sync(int id, int cnt) {
    asm volatile("bar.sync %0, %1;" :: "r"(id), "r"(cnt) : "memory");
}

// ======================================================================
// Encoder: R9 two-group pipeline + TMA bulk publish. NEW: GEMM threads
// re-indexed tid = rg*8 + ks so the 8 k-split lanes of a row-pair are
// in-warp; partials reduced via 3x shfl.bfly, only FINAL sums stored.
// Gate threads read 3 LDS instead of 24.
// ======================================================================
__global__ void __launch_bounds__(TENC, 1) __cluster_dims__(CLUSTER, 1, 1)
enc_kernel(const float* __restrict__ x,
           const float* __restrict__ Wih,
           const float* __restrict__ Whh,
           const float* __restrict__ bih,
           const float* __restrict__ bhh)
{
    __shared__ __align__(16) float  hbuf[NGROUP][2][CLUSTER][NBG][HC]; // 9728 B
    __shared__ __align__(16) float2 finals[NGROUP][2][NBG][RG];        // 3840 B
    __shared__ __align__(16) float  xst[NGROUP][2][NBG][14];           // 896 B
    __shared__ ull mbars[NGROUP][2];

    const int tid = threadIdx.x;
    unsigned rank;
    asm("mov.u32 %0, %%cluster_ctarank;" : "=r"(rank));
    const int bg = (blockIdx.x / CLUSTER) * NB;

    // ---- zero buffers ----
    {
        float* hf = (float*)hbuf;
        for (int i = tid; i < NGROUP * 2 * CLUSTER * NBG * HC; i += TENC) hf[i] = 0.f;
        float* xf = (float*)xst;
        for (int i = tid; i < NGROUP * 2 * NBG * 14; i += TENC) xf[i] = 0.f;
    }
    // prime x(0)
    if (tid < NGROUP * NBG * FEAT) {
        int g = tid / (NBG * FEAT), r = tid % (NBG * FEAT);
        int b = r / FEAT, f = r % FEAT;
        xst[g][0][b][f] = x[((long)(bg + g * NBG + b) * T_STEPS) * FEAT + f];
    }

    const unsigned barb  = smem_u32(&mbars[0][0]);
    const unsigned hbase = smem_u32(hbuf);
    if (tid == 0) {
#pragma unroll
        for (int i = 0; i < 4; i++) {
            mbar_init(barb + i * 8u, 1);
            mbar_expect(barb + i * 8u, EXPB);
        }
    }
    __syncthreads();

    if (tid < NGEMM) {
        // =================== GEMM role (tid = rg*8 + ks) ===================
        const int ks = tid % KSPLIT;      // 0..7, in-warp contiguous
        const int rg = tid / KSPLIT;      // 0..59
        const int row0 = rg * 2;
        ull w0[KSEG2], w1[KSEG2];
        {
            int ga = row0 / ROWP, ia = row0 % ROWP, ua = (int)rank * HC + ia;
            bool oka = (ia < HC) && (ua < HID);
            int gb2 = (row0 + 1) / ROWP, ib = (row0 + 1) % ROWP, ub = (int)rank * HC + ib;
            bool okb = (ib < HC) && (ub < HID);
#pragma unroll
            for (int kp = 0; kp < KSEG2; kp++) {
                int k0 = ks * HC + 2 * kp, k1 = k0 + 1;
                float a0 = (oka && k0 < HID) ? Whh[(ga * HID + ua) * HID + k0] : 0.f;
                float b0 = (oka && k1 < HID) ? Whh[(ga * HID + ua) * HID + k1] : 0.f;
                float a1 = (okb && k0 < HID) ? Whh[(gb2 * HID + ub) * HID + k0] : 0.f;
                float b1 = (okb && k1 < HID) ? Whh[(gb2 * HID + ub) * HID + k1] : 0.f;
                w0[kp] = pk2(a0, b0);
                w1[kp] = pk2(a1, b1);
            }
        }
        __syncthreads();
        cluster_sync_();

        for (int t = 0; t < T_STEPS; t++) {
            const int p = t & 1;
#pragma unroll
            for (int g = 0; g < NGROUP; g++) {
                if (t) {
                    const unsigned bw = barb + (unsigned)(g * 2 + ((t - 1) & 1)) * 8u;
                    mbar_wait(bw, (unsigned)(((t - 1) >> 1) & 1));
                    if (tid == 0) mbar_expect(bw, EXPB);
                }
                // GEMM over buf p: h chunks are rank-major, k = ks*38 + j
                const ull* hp = (const ull*)&hbuf[g][p][ks][0][0];
                ull a00 = 0, a01 = 0, a10 = 0, a11 = 0;
#pragma unroll
                for (int kp = 0; kp < KSEG2; kp++) {
                    ull h0 = hp[kp];
                    ull h1 = hp[kp + KSEG2];
                    fma2(a00, w0[kp], h0); fma2(a01, w1[kp], h0);
                    fma2(a10, w0[kp], h1); fma2(a11, w1[kp], h1);
                }
                // in-warp reduction across the 8 ks lanes (xor 1,2,4)
                float s00 = upks(a00), s01 = upks(a01);
                float s10 = upks(a10), s11 = upks(a11);
#pragma unroll
                for (int d = 1; d < KSPLIT; d <<= 1) {
                    s00 += __shfl_xor_sync(0xffffffffu, s00, d);
                    s01 += __shfl_xor_sync(0xffffffffu, s01, d);
                    s10 += __shfl_xor_sync(0xffffffffu, s10, d);
                    s11 += __shfl_xor_sync(0xffffffffu, s11, d);
                }
                if (ks == 0) {
                    finals[g][p][0][rg] = make_float2(s00, s01);
                    finals[g][p][1][rg] = make_float2(s10, s11);
                }
                bar_arrive(g == 0 ? BAR_PART_A : BAR_PART_B, TENC);
            }
        }
    } else {
        // =================== gate + publish role (96 threads) ===================
        const int gt = tid - NGEMM;
        const int gb2 = gt / HC;          // 0/1 within group
        const int gi_ = gt % HC;
        const int u_g = (int)rank * HC + gi_;
        const bool active = (gt < NBG * HC) && (u_g < HID);

        ull wihr[3][7];
        float brz0 = 0.f, brz1 = 0.f, bin_ = 0.f, bhn_ = 0.f;
        float h_keep[NGROUP] = {0.f, 0.f};
        if (active) {
#pragma unroll
            for (int g = 0; g < 3; g++)
#pragma unroll
                for (int fp = 0; fp < 7; fp++) {
                    float a = Wih[(g * HID + u_g) * FEAT + 2 * fp];
                    float b = (2 * fp + 1 < FEAT) ? Wih[(g * HID + u_g) * FEAT + 2 * fp + 1] : 0.f;
                    wihr[g][fp] = pk2(a, b);
                }
            brz0 = bih[u_g]           + bhh[u_g];
            brz1 = bih[HID + u_g]     + bhh[HID + u_g];
            bin_ = bih[2 * HID + u_g];
            bhn_ = bhh[2 * HID + u_g];
        }
        __syncthreads();
        cluster_sync_();

        for (int t = 0; t < T_STEPS; t++) {
            const int p = t & 1;
            const int buf = p ^ 1;
#pragma unroll
            for (int g = 0; g < NGROUP; g++) {
                // x prefetch LDG issued BEFORE the producer bar (off critical path)
                float xv = 0.f;
                int xb = 0, xf = 0;
                if (gt < NBG * FEAT && t + 1 < T_STEPS) {
                    xb = gt / FEAT; xf = gt % FEAT;
                    xv = __ldg(&x[((long)(bg + g * NBG + xb) * T_STEPS + t + 1) * FEAT + xf]);
                }

                bar_sync(g == 0 ? BAR_PART_A : BAR_PART_B, TENC);

                if (active) {
                    // finals viewed as float[120]: index = gate*40 + gi_
                    const float* pf = (const float*)&finals[g][p][gb2][0];
                    const float s0 = pf[gi_];
                    const float s1 = pf[ROWP + gi_];
                    const float s2 = pf[2 * ROWP + gi_];

                    ull d0 = 0, d1 = 0, d2 = 0;
                    const ull* xq = (const ull*)&xst[g][p][gb2][0];
#pragma unroll
                    for (int fp = 0; fp < 7; fp++) {
                        ull xval = xq[fp];
                        fma2(d0, wihr[0][fp], xval);
                        fma2(d1, wihr[1][fp], xval);
                        fma2(d2, wihr[2][fp], xval);
                    }
                    const float r = sig_f(upks(d0) + s0 + brz0);
                    const float z = sig_f(upks(d1) + s1 + brz1);
                    const float n = tanh_f(upks(d2) + bin_ + r * (s2 + bhn_));
                    const float hn = (1.f - z) * n + z * h_keep[g];
                    h_keep[g] = hn;
                    hbuf[g][buf][rank][gb2][gi_] = hn;   // local chunk write
                }
                if (gt < NBG * FEAT && t + 1 < T_STEPS)
                    xst[g][buf][xb][xf] = xv;

                bar_sync(BAR_GATES, TENC - NGEMM);   // drains STS: chunk visible

                // ---- publish: 8 TMA bulk copies (one per dest), single tx each ----
                if (t + 1 < T_STEPS && gt < CLUSTER) {
                    fence_async_();
                    const unsigned src = hbase
                        + (unsigned)((g * 2 + buf) * CLUSTER + (int)rank) * (unsigned)CHUNKB;
                    const unsigned rb = barb + (unsigned)(g * 2 + (t & 1)) * 8u;
                    bulk_copy_cluster(mapa_(src, gt), src, CHUNKB, mapa_(rb, gt));
                }
            }
        }

        if (active) {
#pragma unroll
            for (int g = 0; g < NGROUP; g++)
                g_hlast[(bg + g * NBG + gb2) * HID + u_g] = h_keep[g];
        }
    }

    // no CTA may exit while sibling TMA copies into it may be in flight
    cluster_sync_();
}

// ======================================================================
// fc + relu
// ======================================================================
__global__ void __launch_bounds__(128) fc_kernel(
    const float* __restrict__ fcW, const float* __restrict__ fcb,
    float* __restrict__ dout, int write_emb)
{
    __shared__ float hs[HID];
    const int b = blockIdx.x;
    const int tid = threadIdx.x;
    for (int k = tid; k < HID; k += 128) hs[k] = g_hlast[b * HID + k];
    __syncthreads();
    for (int j = tid; j < HID; j += 128) {
        float a = fcb[j];
        const float* w = fcW + j * HID;
#pragma unroll 4
        for (int k = 0; k < HID; k++) a = fmaf(w[k], hs[k], a);
        a = fmaxf(a, 0.f);
        g_emb[b * HID + j] = a;
        if (write_emb) dout[OUT_EMB_OFF + b * HID + j] = a;
    }
}

// ======================================================================
// Decoder: one warp per batch element, h broadcast via shfl.
// ======================================================================
__global__ void __launch_bounds__(32) dec_kernel(
    const float* __restrict__ dWih, const float* __restrict__ dWhh,
    const float* __restrict__ dbih, const float* __restrict__ dbhh,
    float* __restrict__ out)
{
    const int b = blockIdx.x;
    const int lane = threadIdx.x;

    float wr[FEAT], wz[FEAT], wn[FEAT];
    float gr0 = 0.f, gz0 = 0.f, gn0 = 0.f, bhn = 0.f, h = 0.f;

    if (lane < FEAT) {
        gr0 = dbih[lane]            + dbhh[lane];
        gz0 = dbih[FEAT + lane]     + dbhh[FEAT + lane];
        gn0 = dbih[2 * FEAT + lane];
        bhn = dbhh[2 * FEAT + lane];
        const float* e  = g_emb + b * HID;
        const float* w0 = dWih + lane * HID;
        const float* w1 = dWih + (FEAT + lane) * HID;
        const float* w2 = dWih + (2 * FEAT + lane) * HID;
#pragma unroll 4
        for (int k = 0; k < HID; k++) {
            float ev = e[k];
            gr0 = fmaf(w0[k], ev, gr0);
            gz0 = fmaf(w1[k], ev, gz0);
            gn0 = fmaf(w2[k], ev, gn0);
        }
#pragma unroll
        for (int k = 0; k < FEAT; k++) {
            wr[k] = dWhh[lane * FEAT + k];
            wz[k] = dWhh[(FEAT + lane) * FEAT + k];
            wn[k] = dWhh[(2 * FEAT + lane) * FEAT + k];
        }
    }

    float* ob = out + (long)b * T_STEPS * FEAT;
    for (int t = 0; t < T_STEPS; t++) {
        float sr = 0.f, sz = 0.f, sn = 0.f;
#pragma unroll
        for (int k = 0; k < FEAT; k++) {
            float hk = __shfl_sync(0xffffffffu, h, k);
            sr = fmaf(wr[k], hk, sr);
            sz = fmaf(wz[k], hk, sz);
            sn = fmaf(wn[k], hk, sn);
        }
        if (lane < FEAT) {
            float r = sig_f(gr0 + sr);
            float z = sig_f(gz0 + sz);
            float n = tanh_f(gn0 + r * (sn + bhn));
            h = (1.f - z) * n + z * h;
            ob[t * FEAT + lane] = h;
        }
    }
}

// ======================================================================
// launch
// ======================================================================
extern "C" void kernel_launch(void* const* d_in, const int* in_sizes, int n_in,
                              void* d_out, int out_size)
{
    const float* x        = (const float*)d_in[0];
    const float* enc_Wih  = (const float*)d_in[1];
    const float* enc_Whh  = (const float*)d_in[2];
    const float* enc_bih  = (const float*)d_in[3];
    const float* enc_bhh  = (const float*)d_in[4];
    const float* fc_W     = (const float*)d_in[5];
    const float* fc_b     = (const float*)d_in[6];
    const float* dec_Wih  = (const float*)d_in[7];
    const float* dec_Whh  = (const float*)d_in[8];
    const float* dec_bih  = (const float*)d_in[9];
    const float* dec_bhh  = (const float*)d_in[10];
    float* out = (float*)d_out;

    const int write_emb = (out_size >= OUT_MAIN + BATCH * HID) ? 1 : 0;

    enc_kernel<<<(BATCH / NB) * CLUSTER, TENC>>>(
        x, enc_Wih, enc_Whh, enc_bih, enc_bhh);
    fc_kernel<<<BATCH, 128>>>(fc_W, fc_b, out, write_emb);
    dec_kernel<<<BATCH, 32>>>(dec_Wih, dec_Whh, dec_bih, dec_bhh, out);
}

// round 16
// speedup vs baseline: 2.2720x; 1.2556x over previous
#include <cuda_runtime.h>
#include <cstdint>

typedef unsigned long long ull;

// ---------------- problem constants ----------------
#define T_STEPS 2048
#define BATCH   64
#define FEAT    13
#define HID     300
#define OUT_MAIN (BATCH*T_STEPS*FEAT)
#define OUT_EMB_OFF OUT_MAIN

// ---------------- encoder config ----------------
#define NCL     16              // logical clusters (CTA octets)
#define OCTET   8
#define NGROUP  2
#define NBG     2               // batch per group
#define NB      (NGROUP*NBG)    // 4 per octet
#define NGEMM   480
#define NGATE   96
#define NLOAD   64              // 2 loader warps (one per group)
#define TENC    (NGEMM+NGATE+NLOAD)  // 640
#define HC      38              // hidden units per CTA chunk
#define ROWP    40
#define KSPLIT  8
#define KSEG2   19
#define RG      60
#define CHUNKF  (NBG*HC)        // 76 floats per CTA per group-step
#define BLOCKF  (OCTET*CHUNKF)  // 608 floats = 2432 B per (octet,group,buf)
#define CNT_PER_STEP 600        // total h values per group-step (2 batches x 300)

#define BAR_PART_A 1            // count 576: 480 gemm arrive + 96 gates sync
#define BAR_PART_B 2
#define BAR_HRDY_A 3            // count 512: 480 gemm sync + 32 loader arrive
#define BAR_HRDY_B 4

__device__ float g_hlast[BATCH*HID];
__device__ float g_emb[BATCH*HID];
// h exchange buffers in global/L2: [octet][group][buf][src_rank][batch][38]
__device__ float g_h[NCL][NGROUP][2][OCTET][NBG][HC];
// monotone counters, one 128B line per (octet, group)
__device__ unsigned g_cnt[NCL][NGROUP][32];

// ---------------- helpers ----------------
__device__ __forceinline__ float sig_f(float x) {
    return __fdividef(1.f, 1.f + __expf(-x));
}
__device__ __forceinline__ float tanh_f(float x) {
    return 1.f - __fdividef(2.f, __expf(2.f * x) + 1.f);
}
__device__ __forceinline__ ull pk2(float lo, float hi) {
    ull r;
    asm("mov.b64 %0, {%1, %2};" : "=l"(r) : "f"(lo), "f"(hi));
    return r;
}
__device__ __forceinline__ void fma2(ull& d, ull a, ull b) {
    asm("fma.rn.f32x2 %0, %1, %2, %0;" : "+l"(d) : "l"(a), "l"(b));
}
__device__ __forceinline__ float upks(ull v) {
    float lo, hi;
    asm("mov.b64 {%0, %1}, %2;" : "=f"(lo), "=f"(hi) : "l"(v));
    return lo + hi;
}
__device__ __forceinline__ void red_release_add(unsigned* p, unsigned v) {
    asm volatile("red.release.gpu.global.add.u32 [%0], %1;" :: "l"(p), "r"(v) : "memory");
}
__device__ __forceinline__ unsigned ld_acq(const unsigned* p) {
    unsigned v;
    asm volatile("ld.acquire.gpu.global.u32 %0, [%1];" : "=r"(v) : "l"(p) : "memory");
    return v;
}
__device__ __forceinline__ void bar_arrive(int id, int cnt) {
    asm volatile("bar.arrive %0, %1;" :: "r"(id), "r"(cnt) : "memory");
}
__device__ __forceinline__ void bar_sync(int id, int cnt) {
    asm volatile("bar.sync %0, %1;" :: "r"(id), "r"(cnt) : "memory");
}

// ======================================================================
// init: zero the counters (every launch; graph-capturable)
// ======================================================================
__global__ void init_kernel() {
    int i = blockIdx.x * blockDim.x + threadIdx.x;
    if (i < NCL * NGROUP * 32) ((unsigned*)g_cnt)[i] = 0;
}

// ======================================================================
// Encoder: NO clusters. h exchanged via L2 (STG + red.release counter);
// dedicated loader warps poll + stage h into SMEM; GEMM/gates as R14.
// Roles: [0,480) GEMM, [480,576) gates, [576,640) loaders (warp/group).
// ======================================================================
__global__ void __launch_bounds__(TENC, 1)
enc_kernel(const float* __restrict__ x,
           const float* __restrict__ Wih,
           const float* __restrict__ Whh,
           const float* __restrict__ bih,
           const float* __restrict__ bhh)
{
    __shared__ __align__(16) float  hbuf[NGROUP][2][OCTET][NBG][HC]; // 9728 B
    __shared__ __align__(16) float2 finals[NGROUP][2][NBG][RG];      // 3840 B
    __shared__ __align__(16) float  xst[NGROUP][2][NBG][14];         // 896 B

    const int tid  = threadIdx.x;
    const int rank = blockIdx.x & 7;
    const int cl   = blockIdx.x >> 3;
    const int bg   = cl * NB;

    // ---- zero hbuf (t=0 h state) + xst ----
    {
        float* hf = (float*)hbuf;
        for (int i = tid; i < NGROUP * 2 * OCTET * NBG * HC; i += TENC) hf[i] = 0.f;
        float* xf = (float*)xst;
        for (int i = tid; i < NGROUP * 2 * NBG * 14; i += TENC) xf[i] = 0.f;
    }
    // prime x(0)
    if (tid < NGROUP * NBG * FEAT) {
        int g = tid / (NBG * FEAT), r = tid % (NBG * FEAT);
        int b = r / FEAT, f = r % FEAT;
        xst[g][0][b][f] = x[((long)(bg + g * NBG + b) * T_STEPS) * FEAT + f];
    }
    __syncthreads();

    if (tid < NGEMM) {
        // =================== GEMM role (tid = rg*8 + ks) ===================
        const int ks = tid % KSPLIT;
        const int rg = tid / KSPLIT;
        const int row0 = rg * 2;
        ull w0[KSEG2], w1[KSEG2];
        {
            int ga = row0 / ROWP, ia = row0 % ROWP, ua = rank * HC + ia;
            bool oka = (ia < HC) && (ua < HID);
            int gb2 = (row0 + 1) / ROWP, ib = (row0 + 1) % ROWP, ub = rank * HC + ib;
            bool okb = (ib < HC) && (ub < HID);
#pragma unroll
            for (int kp = 0; kp < KSEG2; kp++) {
                int k0 = ks * HC + 2 * kp, k1 = k0 + 1;
                float a0 = (oka && k0 < HID) ? Whh[(ga * HID + ua) * HID + k0] : 0.f;
                float b0 = (oka && k1 < HID) ? Whh[(ga * HID + ua) * HID + k1] : 0.f;
                float a1 = (okb && k0 < HID) ? Whh[(gb2 * HID + ub) * HID + k0] : 0.f;
                float b1 = (okb && k1 < HID) ? Whh[(gb2 * HID + ub) * HID + k1] : 0.f;
                w0[kp] = pk2(a0, b0);
                w1[kp] = pk2(a1, b1);
            }
        }

        for (int t = 0; t < T_STEPS; t++) {
            const int p = t & 1;
#pragma unroll
            for (int g = 0; g < NGROUP; g++) {
                bar_sync(g == 0 ? BAR_HRDY_A : BAR_HRDY_B, NGEMM + 32);
                const ull* hp = (const ull*)&hbuf[g][p][ks][0][0];
                ull a00 = 0, a01 = 0, a10 = 0, a11 = 0;
#pragma unroll
                for (int kp = 0; kp < KSEG2; kp++) {
                    ull h0 = hp[kp];
                    ull h1 = hp[kp + KSEG2];
                    fma2(a00, w0[kp], h0); fma2(a01, w1[kp], h0);
                    fma2(a10, w0[kp], h1); fma2(a11, w1[kp], h1);
                }
                float s00 = upks(a00), s01 = upks(a01);
                float s10 = upks(a10), s11 = upks(a11);
#pragma unroll
                for (int d = 1; d < KSPLIT; d <<= 1) {
                    s00 += __shfl_xor_sync(0xffffffffu, s00, d);
                    s01 += __shfl_xor_sync(0xffffffffu, s01, d);
                    s10 += __shfl_xor_sync(0xffffffffu, s10, d);
                    s11 += __shfl_xor_sync(0xffffffffu, s11, d);
                }
                if (ks == 0) {
                    finals[g][p][0][rg] = make_float2(s00, s01);
                    finals[g][p][1][rg] = make_float2(s10, s11);
                }
                bar_arrive(g == 0 ? BAR_PART_A : BAR_PART_B, NGEMM + NGATE);
            }
        }
    } else if (tid < NGEMM + NGATE) {
        // =================== gate + publish role (96 threads) ===================
        const int gt = tid - NGEMM;
        const int gb2 = gt / HC;
        const int gi_ = gt % HC;
        const int u_g = rank * HC + gi_;
        const bool active = (gt < NBG * HC) && (u_g < HID);

        ull wihr[3][7];
        float brz0 = 0.f, brz1 = 0.f, bin_ = 0.f, bhn_ = 0.f;
        float h_keep[NGROUP] = {0.f, 0.f};
        if (active) {
#pragma unroll
            for (int g = 0; g < 3; g++)
#pragma unroll
                for (int fp = 0; fp < 7; fp++) {
                    float a = Wih[(g * HID + u_g) * FEAT + 2 * fp];
                    float b = (2 * fp + 1 < FEAT) ? Wih[(g * HID + u_g) * FEAT + 2 * fp + 1] : 0.f;
                    wihr[g][fp] = pk2(a, b);
                }
            brz0 = bih[u_g]           + bhh[u_g];
            brz1 = bih[HID + u_g]     + bhh[HID + u_g];
            bin_ = bih[2 * HID + u_g];
            bhn_ = bhh[2 * HID + u_g];
        }

        for (int t = 0; t < T_STEPS; t++) {
            const int p = t & 1;
            const int buf = p ^ 1;
#pragma unroll
            for (int g = 0; g < NGROUP; g++) {
                // x prefetch before the producer bar
                float xv = 0.f;
                int xb = 0, xf = 0;
                if (gt < NBG * FEAT && t + 1 < T_STEPS) {
                    xb = gt / FEAT; xf = gt % FEAT;
                    xv = __ldg(&x[((long)(bg + g * NBG + xb) * T_STEPS + t + 1) * FEAT + xf]);
                }

                bar_sync(g == 0 ? BAR_PART_A : BAR_PART_B, NGEMM + NGATE);

                if (active) {
                    const float* pf = (const float*)&finals[g][p][gb2][0];
                    const float s0 = pf[gi_];
                    const float s1 = pf[ROWP + gi_];
                    const float s2 = pf[2 * ROWP + gi_];

                    ull d0 = 0, d1 = 0, d2 = 0;
                    const ull* xq = (const ull*)&xst[g][p][gb2][0];
#pragma unroll
                    for (int fp = 0; fp < 7; fp++) {
                        ull xval = xq[fp];
                        fma2(d0, wihr[0][fp], xval);
                        fma2(d1, wihr[1][fp], xval);
                        fma2(d2, wihr[2][fp], xval);
                    }
                    const float r = sig_f(upks(d0) + s0 + brz0);
                    const float z = sig_f(upks(d1) + s1 + brz1);
                    const float n = tanh_f(upks(d2) + bin_ + r * (s2 + bhn_));
                    const float hn = (1.f - z) * n + z * h_keep[g];
                    h_keep[g] = hn;

                    // publish: one STG + one release-red, fire-and-forget
                    if (t + 1 < T_STEPS) {
                        g_h[cl][g][buf][rank][gb2][gi_] = hn;
                        red_release_add(&g_cnt[cl][g][0], 1u);
                    }
                }
                if (gt < NBG * FEAT && t + 1 < T_STEPS)
                    xst[g][buf][xb][xf] = xv;
            }
        }

        if (active) {
#pragma unroll
            for (int g = 0; g < NGROUP; g++)
                g_hlast[(bg + g * NBG + gb2) * HID + u_g] = h_keep[g];
        }
    } else {
        // =================== loader role: warp per group ===================
        const int lt = tid - NGEMM - NGATE;   // 0..63
        const int g  = lt >> 5;               // group
        const int lw = lt & 31;
        const int bar_h = (g == 0) ? BAR_HRDY_A : BAR_HRDY_B;
        const unsigned* cptr = &g_cnt[cl][g][0];

        // prelude arrive for t = 0 (hbuf pre-zeroed)
        bar_arrive(bar_h, NGEMM + 32);

        for (int t = 1; t < T_STEPS; t++) {
            const unsigned target = (unsigned)CNT_PER_STEP * (unsigned)t;
            while (ld_acq(cptr) < target) { /* spin on L2 line */ }

            const int buf = t & 1;
            const float4* src = (const float4*)&g_h[cl][g][buf][0][0][0];
            float4* dst = (float4*)&hbuf[g][buf][0][0][0];
#pragma unroll
            for (int i = 0; i < 5; i++) {
                int idx = lw + 32 * i;
                if (idx < BLOCKF / 4) dst[idx] = src[idx];
            }
            bar_arrive(bar_h, NGEMM + 32);
        }
    }
}

// ======================================================================
// fc + relu
// ======================================================================
__global__ void __launch_bounds__(128) fc_kernel(
    const float* __restrict__ fcW, const float* __restrict__ fcb,
    float* __restrict__ dout, int write_emb)
{
    __shared__ float hs[HID];
    const int b = blockIdx.x;
    const int tid = threadIdx.x;
    for (int k = tid; k < HID; k += 128) hs[k] = g_hlast[b * HID + k];
    __syncthreads();
    for (int j = tid; j < HID; j += 128) {
        float a = fcb[j];
        const float* w = fcW + j * HID;
#pragma unroll 4
        for (int k = 0; k < HID; k++) a = fmaf(w[k], hs[k], a);
        a = fmaxf(a, 0.f);
        g_emb[b * HID + j] = a;
        if (write_emb) dout[OUT_EMB_OFF + b * HID + j] = a;
    }
}

// ======================================================================
// Decoder: one warp per batch element, h broadcast via shfl.
// ======================================================================
__global__ void __launch_bounds__(32) dec_kernel(
    const float* __restrict__ dWih, const float* __restrict__ dWhh,
    const float* __restrict__ dbih, const float* __restrict__ dbhh,
    float* __restrict__ out)
{
    const int b = blockIdx.x;
    const int lane = threadIdx.x;

    float wr[FEAT], wz[FEAT], wn[FEAT];
    float gr0 = 0.f, gz0 = 0.f, gn0 = 0.f, bhn = 0.f, h = 0.f;

    if (lane < FEAT) {
        gr0 = dbih[lane]            + dbhh[lane];
        gz0 = dbih[FEAT + lane]     + dbhh[FEAT + lane];
        gn0 = dbih[2 * FEAT + lane];
        bhn = dbhh[2 * FEAT + lane];
        const float* e  = g_emb + b * HID;
        const float* w0 = dWih + lane * HID;
        const float* w1 = dWih + (FEAT + lane) * HID;
        const float* w2 = dWih + (2 * FEAT + lane) * HID;
#pragma unroll 4
        for (int k = 0; k < HID; k++) {
            float ev = e[k];
            gr0 = fmaf(w0[k], ev, gr0);
            gz0 = fmaf(w1[k], ev, gz0);
            gn0 = fmaf(w2[k], ev, gn0);
        }
#pragma unroll
        for (int k = 0; k < FEAT; k++) {
            wr[k] = dWhh[lane * FEAT + k];
            wz[k] = dWhh[(FEAT + lane) * FEAT + k];
            wn[k] = dWhh[(2 * FEAT + lane) * FEAT + k];
        }
    }

    float* ob = out + (long)b * T_STEPS * FEAT;
    for (int t = 0; t < T_STEPS; t++) {
        float sr = 0.f, sz = 0.f, sn = 0.f;
#pragma unroll
        for (int k = 0; k < FEAT; k++) {
            float hk = __shfl_sync(0xffffffffu, h, k);
            sr = fmaf(wr[k], hk, sr);
            sz = fmaf(wz[k], hk, sz);
            sn = fmaf(wn[k], hk, sn);
        }
        if (lane < FEAT) {
            float r = sig_f(gr0 + sr);
            float z = sig_f(gz0 + sz);
            float n = tanh_f(gn0 + r * (sn + bhn));
            h = (1.f - z) * n + z * h;
            ob[t * FEAT + lane] = h;
        }
    }
}

// ======================================================================
// launch
// ======================================================================
extern "C" void kernel_launch(void* const* d_in, const int* in_sizes, int n_in,
                              void* d_out, int out_size)
{
    const float* x        = (const float*)d_in[0];
    const float* enc_Wih  = (const float*)d_in[1];
    const float* enc_Whh  = (const float*)d_in[2];
    const float* enc_bih  = (const float*)d_in[3];
    const float* enc_bhh  = (const float*)d_in[4];
    const float* fc_W     = (const float*)d_in[5];
    const float* fc_b     = (const float*)d_in[6];
    const float* dec_Wih  = (const float*)d_in[7];
    const float* dec_Whh  = (const float*)d_in[8];
    const float* dec_bih  = (const float*)d_in[9];
    const float* dec_bhh  = (const float*)d_in[10];
    float* out = (float*)d_out;

    const int write_emb = (out_size >= OUT_MAIN + BATCH * HID) ? 1 : 0;

    init_kernel<<<4, 256>>>();
    enc_kernel<<<NCL * OCTET, TENC>>>(x, enc_Wih, enc_Whh, enc_bih, enc_bhh);
    fc_kernel<<<BATCH, 128>>>(fc_W, fc_b, out, write_emb);
    dec_kernel<<<BATCH, 32>>>(dec_Wih, dec_Whh, dec_bih, dec_bhh, out);
}